// round 1
// baseline (speedup 1.0000x reference)
#include <cuda_runtime.h>

#define NN   32
#define WH   4096
#define CC   256
#define SCALE 0.0625f  // 1/sqrt(256)

// Scratch (device globals — no allocations allowed)
__device__ float g_q[NN * CC];            // leaky(style @ w_dense)
__device__ float g_partS[NN * 16 * CC];   // partial column sums
__device__ float g_palog[NN * WH];        // position-attention logits
__device__ float g_ca[NN * CC];           // channel attention (softmax)
__device__ float g_pa[NN * WH];           // position attention (softmax)

// ---------------------------------------------------------------------------
// K1: q[n,c] = leaky_relu_0.3( sum_k style[n,k] * w_dense[k,c] )
// grid=32, block=256
// ---------------------------------------------------------------------------
__global__ void k_q(const float* __restrict__ style, const float* __restrict__ wd) {
    int n = blockIdx.x, c = threadIdx.x;
    __shared__ float s[CC];
    s[c] = style[n * CC + c];
    __syncthreads();
    float acc = 0.f;
#pragma unroll 8
    for (int k = 0; k < CC; k++)
        acc = fmaf(s[k], wd[k * CC + c], acc);
    g_q[n * CC + c] = acc > 0.f ? acc : 0.3f * acc;
}

// ---------------------------------------------------------------------------
// K2: one pass over inputs. Produces pa_logits[n,p] and partial column sums.
// grid=(16 chunks, 32 n), block=256 (8 warps, 32 rows/warp)
// ---------------------------------------------------------------------------
__global__ void k_pa_colsum(const float* __restrict__ in) {
    int n = blockIdx.y, chunk = blockIdx.x;
    int tid = threadIdx.x, lane = tid & 31, w = tid >> 5;

    const float4* q4 = reinterpret_cast<const float4*>(g_q + (size_t)n * CC);
    float4 qa = q4[lane * 2], qb = q4[lane * 2 + 1];

    float4 cs0 = {0.f, 0.f, 0.f, 0.f}, cs1 = {0.f, 0.f, 0.f, 0.f};
    int pbase = chunk * 256 + w * 32;
    const float4* base4 =
        reinterpret_cast<const float4*>(in + ((size_t)n * WH + pbase) * CC);

    for (int i = 0; i < 32; i++) {
        const float4* r = base4 + (size_t)i * (CC / 4);
        float4 v0 = r[lane * 2], v1 = r[lane * 2 + 1];
        float d = v0.x * qa.x + v0.y * qa.y + v0.z * qa.z + v0.w * qa.w
                + v1.x * qb.x + v1.y * qb.y + v1.z * qb.z + v1.w * qb.w;
        cs0.x += v0.x; cs0.y += v0.y; cs0.z += v0.z; cs0.w += v0.w;
        cs1.x += v1.x; cs1.y += v1.y; cs1.z += v1.z; cs1.w += v1.w;
#pragma unroll
        for (int o = 16; o; o >>= 1) d += __shfl_xor_sync(0xffffffffu, d, o);
        if (lane == 0) g_palog[(size_t)n * WH + pbase + i] = d * SCALE;
    }

    __shared__ float sm[8 * CC];
    float* smw = sm + w * CC + lane * 8;
    smw[0] = cs0.x; smw[1] = cs0.y; smw[2] = cs0.z; smw[3] = cs0.w;
    smw[4] = cs1.x; smw[5] = cs1.y; smw[6] = cs1.z; smw[7] = cs1.w;
    __syncthreads();
    float ssum = 0.f;
#pragma unroll
    for (int ww = 0; ww < 8; ww++) ssum += sm[ww * CC + tid];
    g_partS[((size_t)n * 16 + chunk) * CC + tid] = ssum;
}

// ---------------------------------------------------------------------------
// K3a: channel attention. ca = softmax_c( S[n,c] * q[n,c] * scale )
// grid=32, block=256
// ---------------------------------------------------------------------------
__global__ void k_ca() {
    int n = blockIdx.x, c = threadIdx.x;
    float S = 0.f;
#pragma unroll
    for (int k = 0; k < 16; k++) S += g_partS[((size_t)n * 16 + k) * CC + c];
    float logit = S * g_q[n * CC + c] * SCALE;

    __shared__ float red[CC];
    red[c] = logit; __syncthreads();
    for (int s = 128; s; s >>= 1) {
        if (c < s) red[c] = fmaxf(red[c], red[c + s]);
        __syncthreads();
    }
    float m = red[0]; __syncthreads();
    float e = expf(logit - m);
    red[c] = e; __syncthreads();
    for (int s = 128; s; s >>= 1) {
        if (c < s) red[c] += red[c + s];
        __syncthreads();
    }
    g_ca[n * CC + c] = e / red[0];
}

// ---------------------------------------------------------------------------
// K3b: position attention. pa = softmax over 4096 positions per n.
// grid=32, block=256, 16 values/thread
// ---------------------------------------------------------------------------
__global__ void k_pa() {
    int n = blockIdx.x, tid = threadIdx.x;
    float v[16];
    float m = -1e30f;
#pragma unroll
    for (int i = 0; i < 16; i++) {
        v[i] = g_palog[(size_t)n * WH + i * 256 + tid];
        m = fmaxf(m, v[i]);
    }
    __shared__ float red[256];
    red[tid] = m; __syncthreads();
    for (int s = 128; s; s >>= 1) {
        if (tid < s) red[tid] = fmaxf(red[tid], red[tid + s]);
        __syncthreads();
    }
    m = red[0]; __syncthreads();
    float sum = 0.f;
#pragma unroll
    for (int i = 0; i < 16; i++) { v[i] = expf(v[i] - m); sum += v[i]; }
    red[tid] = sum; __syncthreads();
    for (int s = 128; s; s >>= 1) {
        if (tid < s) red[tid] += red[tid + s];
        __syncthreads();
    }
    float r = 1.f / red[0];
#pragma unroll
    for (int i = 0; i < 16; i++)
        g_pa[(size_t)n * WH + i * 256 + tid] = v[i] * r;
}

// ---------------------------------------------------------------------------
// K4: batched GEMM. out[n,p,co] = pa[n,p] * leaky0.1( sum_ci in[n,p,ci]*ca[n,ci]*w[ci,co] )
// Tile 128x128x16, 8x8 per thread. grid=(32, 2, 32n), block=256.
// ---------------------------------------------------------------------------
__global__ void __launch_bounds__(256, 2)
k_conv(const float* __restrict__ in, const float* __restrict__ wc,
       float* __restrict__ out) {
    const int n  = blockIdx.z;
    const int m0 = blockIdx.x * 128;
    const int n0 = blockIdx.y * 128;

    __shared__ float As[16][132];   // padded: transposed A tile (k-major)
    __shared__ float Bs[16][128];
    __shared__ float cas[CC];

    const int tid = threadIdx.x;
    cas[tid] = g_ca[n * CC + tid];

    const float* A = in + (size_t)n * WH * CC;

    float acc[8][8];
#pragma unroll
    for (int i = 0; i < 8; i++)
#pragma unroll
        for (int j = 0; j < 8; j++) acc[i][j] = 0.f;

    const int tx = tid & 15, ty = tid >> 4;
    const int kq = tid & 3,  ma = tid >> 2;     // A load mapping
    const int bn = tid & 127, bk = tid >> 7;    // B load mapping

    for (int k0 = 0; k0 < CC; k0 += 16) {
        __syncthreads();
        // Load+fold-ca A tile: 128 rows x 16 k, float4 along k
#pragma unroll
        for (int i = 0; i < 2; i++) {
            int m = ma + 64 * i;
            float4 v = *reinterpret_cast<const float4*>(
                &A[(size_t)(m0 + m) * CC + k0 + kq * 4]);
            v.x *= cas[k0 + kq * 4 + 0];
            v.y *= cas[k0 + kq * 4 + 1];
            v.z *= cas[k0 + kq * 4 + 2];
            v.w *= cas[k0 + kq * 4 + 3];
            As[kq * 4 + 0][m] = v.x;
            As[kq * 4 + 1][m] = v.y;
            As[kq * 4 + 2][m] = v.z;
            As[kq * 4 + 3][m] = v.w;
        }
        // Load B tile: 16 k x 128 co
#pragma unroll
        for (int i = 0; i < 8; i++)
            Bs[bk + 2 * i][bn] = wc[(size_t)(k0 + bk + 2 * i) * CC + n0 + bn];
        __syncthreads();

#pragma unroll
        for (int k = 0; k < 16; k++) {
            float4 a0 = *reinterpret_cast<const float4*>(&As[k][ty * 8]);
            float4 a1 = *reinterpret_cast<const float4*>(&As[k][ty * 8 + 4]);
            float4 b0 = *reinterpret_cast<const float4*>(&Bs[k][tx * 8]);
            float4 b1 = *reinterpret_cast<const float4*>(&Bs[k][tx * 8 + 4]);
            float a[8] = {a0.x, a0.y, a0.z, a0.w, a1.x, a1.y, a1.z, a1.w};
            float b[8] = {b0.x, b0.y, b0.z, b0.w, b1.x, b1.y, b1.z, b1.w};
#pragma unroll
            for (int i = 0; i < 8; i++)
#pragma unroll
                for (int j = 0; j < 8; j++)
                    acc[i][j] = fmaf(a[i], b[j], acc[i][j]);
        }
    }

    // Epilogue: leaky_relu(0.1) then scale by pa (valid since pa > 0)
#pragma unroll
    for (int i = 0; i < 8; i++) {
        int m = m0 + ty * 8 + i;
        float pav = g_pa[(size_t)n * WH + m];
        float o[8];
#pragma unroll
        for (int j = 0; j < 8; j++) {
            float v = acc[i][j];
            o[j] = (v > 0.f ? v : 0.1f * v) * pav;
        }
        float* op = out + ((size_t)n * WH + m) * CC + n0 + tx * 8;
        *reinterpret_cast<float4*>(op)     = make_float4(o[0], o[1], o[2], o[3]);
        *reinterpret_cast<float4*>(op + 4) = make_float4(o[4], o[5], o[6], o[7]);
    }
}

// ---------------------------------------------------------------------------
extern "C" void kernel_launch(void* const* d_in, const int* in_sizes, int n_in,
                              void* d_out, int out_size) {
    const float* in    = (const float*)d_in[0];  // [32,64,64,256]
    const float* style = (const float*)d_in[1];  // [32,256]
    const float* wd    = (const float*)d_in[2];  // [256,256]
    const float* wc    = (const float*)d_in[3];  // [1,1,256,256] -> [ci][co]
    float* out = (float*)d_out;

    k_q<<<NN, CC>>>(style, wd);
    k_pa_colsum<<<dim3(16, NN), 256>>>(in);
    k_ca<<<NN, CC>>>();
    k_pa<<<NN, 256>>>();
    k_conv<<<dim3(WH / 128, CC / 128, NN), 256>>>(in, wc, out);
}

// round 3
// speedup vs baseline: 1.7888x; 1.7888x over previous
#include <cuda_runtime.h>
#include <cuda_bf16.h>
#include <cstdint>

#define NN   32
#define WH   4096
#define CC   256
#define SCALE 0.0625f  // 1/sqrt(256)

// Scratch (device globals — no allocations allowed)
__device__ float g_q[NN * CC];
__device__ float g_partS[NN * 16 * CC];
__device__ float g_palog[NN * WH];
__device__ float g_ca[NN * CC];
__device__ float g_pa[NN * WH];
// Pre-split weights, transposed to [co][ci], bf16 hi/lo
__device__ __align__(16) unsigned short g_Bh[CC * CC];
__device__ __align__(16) unsigned short g_Bl[CC * CC];

// ---------------------------------------------------------------------------
// MMA helpers (baseline PTX — works on plain sm_103 target)
// ---------------------------------------------------------------------------
__device__ __forceinline__ void ldm4(uint32_t* r, uint32_t addr) {
    asm volatile("ldmatrix.sync.aligned.m8n8.x4.shared.b16 {%0,%1,%2,%3}, [%4];"
                 : "=r"(r[0]), "=r"(r[1]), "=r"(r[2]), "=r"(r[3]) : "r"(addr));
}
__device__ __forceinline__ void mma_bf16(float* c, const uint32_t* a,
                                         uint32_t b0, uint32_t b1) {
    asm volatile(
        "mma.sync.aligned.m16n8k16.row.col.f32.bf16.bf16.f32 "
        "{%0,%1,%2,%3}, {%4,%5,%6,%7}, {%8,%9}, {%0,%1,%2,%3};"
        : "+f"(c[0]), "+f"(c[1]), "+f"(c[2]), "+f"(c[3])
        : "r"(a[0]), "r"(a[1]), "r"(a[2]), "r"(a[3]), "r"(b0), "r"(b1));
}
__device__ __forceinline__ uint32_t pack_bf(float a, float b) {
    __nv_bfloat162 t = __floats2bfloat162_rn(a, b);
    return *reinterpret_cast<uint32_t*>(&t);
}

// ---------------------------------------------------------------------------
// K1: q[n,c] = leaky_relu_0.3( style @ w_dense )
// ---------------------------------------------------------------------------
__global__ void k_q(const float* __restrict__ style, const float* __restrict__ wd) {
    int n = blockIdx.x, c = threadIdx.x;
    __shared__ float s[CC];
    s[c] = style[n * CC + c];
    __syncthreads();
    float acc = 0.f;
#pragma unroll 8
    for (int k = 0; k < CC; k++) acc = fmaf(s[k], wd[k * CC + c], acc);
    g_q[n * CC + c] = acc > 0.f ? acc : 0.3f * acc;
}

// ---------------------------------------------------------------------------
// K_prepB: split w_conv [ci][co] -> bf16 hi/lo, transposed to [co][ci]
// ---------------------------------------------------------------------------
__global__ void k_prepB(const float* __restrict__ wc) {
    int n = blockIdx.x;   // co
    int k = threadIdx.x;  // ci
    float v = wc[k * CC + n];
    __nv_bfloat16 h = __float2bfloat16_rn(v);
    __nv_bfloat16 l = __float2bfloat16_rn(v - __bfloat162float(h));
    g_Bh[n * CC + k] = __bfloat16_as_ushort(h);
    g_Bl[n * CC + k] = __bfloat16_as_ushort(l);
}

// ---------------------------------------------------------------------------
// K2: one pass over inputs: pa_logits + partial column sums
// ---------------------------------------------------------------------------
__global__ void k_pa_colsum(const float* __restrict__ in) {
    int n = blockIdx.y, chunk = blockIdx.x;
    int tid = threadIdx.x, lane = tid & 31, w = tid >> 5;

    const float4* q4 = reinterpret_cast<const float4*>(g_q + (size_t)n * CC);
    float4 qa = q4[lane * 2], qb = q4[lane * 2 + 1];

    float4 cs0 = {0.f, 0.f, 0.f, 0.f}, cs1 = {0.f, 0.f, 0.f, 0.f};
    int pbase = chunk * 256 + w * 32;
    const float4* base4 =
        reinterpret_cast<const float4*>(in + ((size_t)n * WH + pbase) * CC);

    for (int i = 0; i < 32; i++) {
        const float4* r = base4 + (size_t)i * (CC / 4);
        float4 v0 = r[lane * 2], v1 = r[lane * 2 + 1];
        float d = v0.x * qa.x + v0.y * qa.y + v0.z * qa.z + v0.w * qa.w
                + v1.x * qb.x + v1.y * qb.y + v1.z * qb.z + v1.w * qb.w;
        cs0.x += v0.x; cs0.y += v0.y; cs0.z += v0.z; cs0.w += v0.w;
        cs1.x += v1.x; cs1.y += v1.y; cs1.z += v1.z; cs1.w += v1.w;
#pragma unroll
        for (int o = 16; o; o >>= 1) d += __shfl_xor_sync(0xffffffffu, d, o);
        if (lane == 0) g_palog[(size_t)n * WH + pbase + i] = d * SCALE;
    }

    __shared__ float sm[8 * CC];
    float* smw = sm + w * CC + lane * 8;
    smw[0] = cs0.x; smw[1] = cs0.y; smw[2] = cs0.z; smw[3] = cs0.w;
    smw[4] = cs1.x; smw[5] = cs1.y; smw[6] = cs1.z; smw[7] = cs1.w;
    __syncthreads();
    float ssum = 0.f;
#pragma unroll
    for (int ww = 0; ww < 8; ww++) ssum += sm[ww * CC + tid];
    g_partS[((size_t)n * 16 + chunk) * CC + tid] = ssum;
}

// ---------------------------------------------------------------------------
// K3a: channel softmax
// ---------------------------------------------------------------------------
__global__ void k_ca() {
    int n = blockIdx.x, c = threadIdx.x;
    float S = 0.f;
#pragma unroll
    for (int k = 0; k < 16; k++) S += g_partS[((size_t)n * 16 + k) * CC + c];
    float logit = S * g_q[n * CC + c] * SCALE;

    __shared__ float red[CC];
    red[c] = logit; __syncthreads();
    for (int s = 128; s; s >>= 1) {
        if (c < s) red[c] = fmaxf(red[c], red[c + s]);
        __syncthreads();
    }
    float m = red[0]; __syncthreads();
    float e = expf(logit - m);
    red[c] = e; __syncthreads();
    for (int s = 128; s; s >>= 1) {
        if (c < s) red[c] += red[c + s];
        __syncthreads();
    }
    g_ca[n * CC + c] = e / red[0];
}

// ---------------------------------------------------------------------------
// K3b: position softmax over 4096
// ---------------------------------------------------------------------------
__global__ void k_pa() {
    int n = blockIdx.x, tid = threadIdx.x;
    float v[16];
    float m = -1e30f;
#pragma unroll
    for (int i = 0; i < 16; i++) {
        v[i] = g_palog[(size_t)n * WH + i * 256 + tid];
        m = fmaxf(m, v[i]);
    }
    __shared__ float red[256];
    red[tid] = m; __syncthreads();
    for (int s = 128; s; s >>= 1) {
        if (tid < s) red[tid] = fmaxf(red[tid], red[tid + s]);
        __syncthreads();
    }
    m = red[0]; __syncthreads();
    float sum = 0.f;
#pragma unroll
    for (int i = 0; i < 16; i++) { v[i] = expf(v[i] - m); sum += v[i]; }
    red[tid] = sum; __syncthreads();
    for (int s = 128; s; s >>= 1) {
        if (tid < s) red[tid] += red[tid + s];
        __syncthreads();
    }
    float r = 1.f / red[0];
#pragma unroll
    for (int i = 0; i < 16; i++)
        g_pa[(size_t)n * WH + i * 256 + tid] = v[i] * r;
}

// ---------------------------------------------------------------------------
// K4: HMMA split-bf16 GEMM.
// D[128,128] = (A*ca)[128,K] @ W[K,128], 3-term split, fp32 reg accum.
// grid=(32 mtiles, 2 ntiles, 32 batch), block=256 (8 warps, warp tile 32x64).
// Smem tiles padded to 40 halves/row (20-bank offset => conflict-free ldmatrix).
// ---------------------------------------------------------------------------
#define KC 32
#define AST 40   // padded row stride in halves (80 bytes)

__global__ void __launch_bounds__(256)
k_conv_mma(const float* __restrict__ in, float* __restrict__ out) {
    __shared__ unsigned short Ah[128 * AST];
    __shared__ unsigned short Al[128 * AST];
    __shared__ unsigned short Bh[128 * AST];
    __shared__ unsigned short Bl[128 * AST];
    __shared__ float cas[CC];

    const int tid = threadIdx.x, lane = tid & 31, wid = tid >> 5;
    const int nb = blockIdx.z;
    const int m0 = blockIdx.x * 128;
    const int n0 = blockIdx.y * 128;
    const int warp_m = (wid & 3) * 32;
    const int warp_n = (wid >> 2) * 64;

    cas[tid] = g_ca[nb * CC + tid];

    const float* A = in + ((size_t)nb * WH + m0) * CC;

    const uint32_t sAh = (uint32_t)__cvta_generic_to_shared(Ah);
    const uint32_t sAl = (uint32_t)__cvta_generic_to_shared(Al);
    const uint32_t sBh = (uint32_t)__cvta_generic_to_shared(Bh);
    const uint32_t sBl = (uint32_t)__cvta_generic_to_shared(Bl);

    // ldmatrix per-thread address offsets (bytes)
    const int q = lane >> 3;
    const uint32_t aRow = (uint32_t)(warp_m + (lane & 7) + (q & 1) * 8) * 80
                        + (uint32_t)((q >> 1) * 8) * 2;
    const uint32_t bRow = (uint32_t)(warp_n + (lane & 7) + (q >> 1) * 8) * 80
                        + (uint32_t)((q & 1) * 8) * 2;

    // Global-load mappings
    const int rA = tid >> 1, sA = tid & 1;   // A: row, 16-k segment
    const int nB = tid >> 1, uB = tid & 1;   // B: row, 16-k segment

    float acc[2][8][4];
#pragma unroll
    for (int i = 0; i < 2; i++)
#pragma unroll
        for (int j = 0; j < 8; j++)
#pragma unroll
            for (int t = 0; t < 4; t++) acc[i][j][t] = 0.f;

    for (int c = 0; c < CC / KC; c++) {
        __syncthreads();
        // --- A chunk: fp32 load, fold ca, split bf16 hi/lo, padded store ---
        {
            const float* Ar = A + (size_t)rA * CC + c * KC + sA * 16;
            const float* cp = cas + c * KC + sA * 16;
            uint32_t hi[8], lo[8];
#pragma unroll
            for (int j = 0; j < 4; j++) {
                float4 v = *reinterpret_cast<const float4*>(Ar + j * 4);
                float a0 = v.x * cp[j * 4 + 0];
                float a1 = v.y * cp[j * 4 + 1];
                float a2 = v.z * cp[j * 4 + 2];
                float a3 = v.w * cp[j * 4 + 3];
                __nv_bfloat16 h0 = __float2bfloat16_rn(a0);
                __nv_bfloat16 h1 = __float2bfloat16_rn(a1);
                __nv_bfloat16 h2 = __float2bfloat16_rn(a2);
                __nv_bfloat16 h3 = __float2bfloat16_rn(a3);
                hi[j * 2 + 0] = (uint32_t)__bfloat16_as_ushort(h0)
                              | ((uint32_t)__bfloat16_as_ushort(h1) << 16);
                hi[j * 2 + 1] = (uint32_t)__bfloat16_as_ushort(h2)
                              | ((uint32_t)__bfloat16_as_ushort(h3) << 16);
                lo[j * 2 + 0] = pack_bf(a0 - __bfloat162float(h0),
                                        a1 - __bfloat162float(h1));
                lo[j * 2 + 1] = pack_bf(a2 - __bfloat162float(h2),
                                        a3 - __bfloat162float(h3));
            }
            uint4* dh = reinterpret_cast<uint4*>(&Ah[rA * AST + sA * 16]);
            uint4* dl = reinterpret_cast<uint4*>(&Al[rA * AST + sA * 16]);
            dh[0] = make_uint4(hi[0], hi[1], hi[2], hi[3]);
            dh[1] = make_uint4(hi[4], hi[5], hi[6], hi[7]);
            dl[0] = make_uint4(lo[0], lo[1], lo[2], lo[3]);
            dl[1] = make_uint4(lo[4], lo[5], lo[6], lo[7]);
        }
        // --- B chunk: flat copy (L2-hot) ---
        {
            size_t gidx = (size_t)(n0 + nB) * CC + c * KC + uB * 16;
            const uint4* gh = reinterpret_cast<const uint4*>(g_Bh + gidx);
            const uint4* gl = reinterpret_cast<const uint4*>(g_Bl + gidx);
            uint4* dh = reinterpret_cast<uint4*>(&Bh[nB * AST + uB * 16]);
            uint4* dl = reinterpret_cast<uint4*>(&Bl[nB * AST + uB * 16]);
            dh[0] = gh[0]; dh[1] = gh[1];
            dl[0] = gl[0]; dl[1] = gl[1];
        }
        __syncthreads();

        // --- MMA: 2 k-steps x (AhBh + AlBh + AhBl) ---
#pragma unroll
        for (int ks = 0; ks < 2; ks++) {
            const uint32_t ko = ks * 32;
            uint32_t ah[2][4], al[2][4];
            ldm4(ah[0], sAh + aRow + ko);
            ldm4(ah[1], sAh + aRow + 1280 + ko);
            ldm4(al[0], sAl + aRow + ko);
            ldm4(al[1], sAl + aRow + 1280 + ko);
#pragma unroll
            for (int p = 0; p < 4; p++) {
                uint32_t bb[4];
                ldm4(bb, sBh + bRow + p * 1280 + ko);
                mma_bf16(acc[0][2 * p],     ah[0], bb[0], bb[1]);
                mma_bf16(acc[0][2 * p + 1], ah[0], bb[2], bb[3]);
                mma_bf16(acc[1][2 * p],     ah[1], bb[0], bb[1]);
                mma_bf16(acc[1][2 * p + 1], ah[1], bb[2], bb[3]);
                mma_bf16(acc[0][2 * p],     al[0], bb[0], bb[1]);
                mma_bf16(acc[0][2 * p + 1], al[0], bb[2], bb[3]);
                mma_bf16(acc[1][2 * p],     al[1], bb[0], bb[1]);
                mma_bf16(acc[1][2 * p + 1], al[1], bb[2], bb[3]);
                ldm4(bb, sBl + bRow + p * 1280 + ko);
                mma_bf16(acc[0][2 * p],     ah[0], bb[0], bb[1]);
                mma_bf16(acc[0][2 * p + 1], ah[0], bb[2], bb[3]);
                mma_bf16(acc[1][2 * p],     ah[1], bb[0], bb[1]);
                mma_bf16(acc[1][2 * p + 1], ah[1], bb[2], bb[3]);
            }
        }
    }

    // --- Epilogue: leaky0.1 then *pa, fp32 stores ---
#pragma unroll
    for (int mt = 0; mt < 2; mt++) {
        int mrow = m0 + warp_m + mt * 16 + (lane >> 2);
        float pa0 = g_pa[(size_t)nb * WH + mrow];
        float pa1 = g_pa[(size_t)nb * WH + mrow + 8];
        float* o0 = out + ((size_t)nb * WH + mrow) * CC + n0 + warp_n + (lane & 3) * 2;
        float* o1 = o0 + 8 * CC;
#pragma unroll
        for (int nt = 0; nt < 8; nt++) {
            float v0 = acc[mt][nt][0], v1 = acc[mt][nt][1];
            float v2 = acc[mt][nt][2], v3 = acc[mt][nt][3];
            v0 = (v0 > 0.f ? v0 : 0.1f * v0) * pa0;
            v1 = (v1 > 0.f ? v1 : 0.1f * v1) * pa0;
            v2 = (v2 > 0.f ? v2 : 0.1f * v2) * pa1;
            v3 = (v3 > 0.f ? v3 : 0.1f * v3) * pa1;
            *reinterpret_cast<float2*>(o0 + nt * 8) = make_float2(v0, v1);
            *reinterpret_cast<float2*>(o1 + nt * 8) = make_float2(v2, v3);
        }
    }
}

// ---------------------------------------------------------------------------
extern "C" void kernel_launch(void* const* d_in, const int* in_sizes, int n_in,
                              void* d_out, int out_size) {
    const float* in    = (const float*)d_in[0];  // [32,64,64,256]
    const float* style = (const float*)d_in[1];  // [32,256]
    const float* wd    = (const float*)d_in[2];  // [256,256]
    const float* wc    = (const float*)d_in[3];  // [1,1,256,256] -> [ci][co]
    float* out = (float*)d_out;

    k_q<<<NN, CC>>>(style, wd);
    k_prepB<<<CC, CC>>>(wc);
    k_pa_colsum<<<dim3(16, NN), 256>>>(in);
    k_ca<<<NN, CC>>>();
    k_pa<<<NN, 256>>>();
    k_conv_mma<<<dim3(WH / 128, CC / 128, NN), 256>>>(in, out);
}

// round 4
// speedup vs baseline: 2.0118x; 1.1247x over previous
#include <cuda_runtime.h>
#include <cuda_fp16.h>
#include <cstdint>

#define NN   32
#define WH   4096
#define CC   256
#define SCALE 0.0625f  // 1/sqrt(256)

// Scratch (device globals — no allocations allowed)
__device__ float g_q[NN * CC];
__device__ float g_partS[NN * 16 * CC];
__device__ float g_palog[NN * WH];
__device__ float g_ca[NN * CC];
__device__ float g_pa[NN * WH];
// Pre-split weights, transposed to [co][ci], fp16 hi + fp16 lo (exact to ~2^-22)
__device__ __align__(16) unsigned short g_Bh[CC * CC];
__device__ __align__(16) unsigned short g_Bl[CC * CC];

// ---------------------------------------------------------------------------
// MMA helpers (baseline PTX — plain sm_103 target)
// ---------------------------------------------------------------------------
__device__ __forceinline__ void ldm4(uint32_t* r, uint32_t addr) {
    asm volatile("ldmatrix.sync.aligned.m8n8.x4.shared.b16 {%0,%1,%2,%3}, [%4];"
                 : "=r"(r[0]), "=r"(r[1]), "=r"(r[2]), "=r"(r[3]) : "r"(addr));
}
__device__ __forceinline__ void mma_f16(float* c, const uint32_t* a,
                                        uint32_t b0, uint32_t b1) {
    asm volatile(
        "mma.sync.aligned.m16n8k16.row.col.f32.f16.f16.f32 "
        "{%0,%1,%2,%3}, {%4,%5,%6,%7}, {%8,%9}, {%0,%1,%2,%3};"
        : "+f"(c[0]), "+f"(c[1]), "+f"(c[2]), "+f"(c[3])
        : "r"(a[0]), "r"(a[1]), "r"(a[2]), "r"(a[3]), "r"(b0), "r"(b1));
}
__device__ __forceinline__ uint32_t pack_h2(float a, float b) {
    __half2 t = __floats2half2_rn(a, b);
    return *reinterpret_cast<uint32_t*>(&t);
}

// ---------------------------------------------------------------------------
// K_prep (fused): blocks 0..31 -> q = leaky0.3(style@wd); blocks 32..287 ->
// split w_conv [ci][co] into fp16 hi/lo transposed to [co][ci].
// ---------------------------------------------------------------------------
__global__ void k_prep(const float* __restrict__ style,
                       const float* __restrict__ wd,
                       const float* __restrict__ wc) {
    int b = blockIdx.x, t = threadIdx.x;
    if (b < NN) {
        __shared__ float s[CC];
        s[t] = style[b * CC + t];
        __syncthreads();
        float acc = 0.f;
#pragma unroll 8
        for (int k = 0; k < CC; k++) acc = fmaf(s[k], wd[k * CC + t], acc);
        g_q[b * CC + t] = acc > 0.f ? acc : 0.3f * acc;
    } else {
        int n = b - NN;          // co
        float v = wc[t * CC + n];  // t = ci
        __half h = __float2half_rn(v);
        __half l = __float2half_rn(v - __half2float(h));
        g_Bh[n * CC + t] = __half_as_ushort(h);
        g_Bl[n * CC + t] = __half_as_ushort(l);
    }
}

// ---------------------------------------------------------------------------
// K2: one pass over inputs: pa_logits + partial column sums
// ---------------------------------------------------------------------------
__global__ void k_pa_colsum(const float* __restrict__ in) {
    int n = blockIdx.y, chunk = blockIdx.x;
    int tid = threadIdx.x, lane = tid & 31, w = tid >> 5;

    const float4* q4 = reinterpret_cast<const float4*>(g_q + (size_t)n * CC);
    float4 qa = q4[lane * 2], qb = q4[lane * 2 + 1];

    float4 cs0 = {0.f, 0.f, 0.f, 0.f}, cs1 = {0.f, 0.f, 0.f, 0.f};
    int pbase = chunk * 256 + w * 32;
    const float4* base4 =
        reinterpret_cast<const float4*>(in + ((size_t)n * WH + pbase) * CC);

    for (int i = 0; i < 32; i++) {
        const float4* r = base4 + (size_t)i * (CC / 4);
        float4 v0 = r[lane * 2], v1 = r[lane * 2 + 1];
        float d = v0.x * qa.x + v0.y * qa.y + v0.z * qa.z + v0.w * qa.w
                + v1.x * qb.x + v1.y * qb.y + v1.z * qb.z + v1.w * qb.w;
        cs0.x += v0.x; cs0.y += v0.y; cs0.z += v0.z; cs0.w += v0.w;
        cs1.x += v1.x; cs1.y += v1.y; cs1.z += v1.z; cs1.w += v1.w;
#pragma unroll
        for (int o = 16; o; o >>= 1) d += __shfl_xor_sync(0xffffffffu, d, o);
        if (lane == 0) g_palog[(size_t)n * WH + pbase + i] = d * SCALE;
    }

    __shared__ float sm[8 * CC];
    float* smw = sm + w * CC + lane * 8;
    smw[0] = cs0.x; smw[1] = cs0.y; smw[2] = cs0.z; smw[3] = cs0.w;
    smw[4] = cs1.x; smw[5] = cs1.y; smw[6] = cs1.z; smw[7] = cs1.w;
    __syncthreads();
    float ssum = 0.f;
#pragma unroll
    for (int ww = 0; ww < 8; ww++) ssum += sm[ww * CC + tid];
    g_partS[((size_t)n * 16 + chunk) * CC + tid] = ssum;
}

// ---------------------------------------------------------------------------
// K_soft (fused): blocks 0..31 -> channel softmax; 32..63 -> position softmax
// ---------------------------------------------------------------------------
__global__ void k_soft() {
    int b = blockIdx.x, tid = threadIdx.x;
    __shared__ float red[256];
    if (b < NN) {
        int n = b;
        float S = 0.f;
#pragma unroll
        for (int k = 0; k < 16; k++) S += g_partS[((size_t)n * 16 + k) * CC + tid];
        float logit = S * g_q[n * CC + tid] * SCALE;
        red[tid] = logit; __syncthreads();
        for (int s = 128; s; s >>= 1) {
            if (tid < s) red[tid] = fmaxf(red[tid], red[tid + s]);
            __syncthreads();
        }
        float m = red[0]; __syncthreads();
        float e = expf(logit - m);
        red[tid] = e; __syncthreads();
        for (int s = 128; s; s >>= 1) {
            if (tid < s) red[tid] += red[tid + s];
            __syncthreads();
        }
        g_ca[n * CC + tid] = e / red[0];
    } else {
        int n = b - NN;
        float v[16];
        float m = -1e30f;
#pragma unroll
        for (int i = 0; i < 16; i++) {
            v[i] = g_palog[(size_t)n * WH + i * 256 + tid];
            m = fmaxf(m, v[i]);
        }
        red[tid] = m; __syncthreads();
        for (int s = 128; s; s >>= 1) {
            if (tid < s) red[tid] = fmaxf(red[tid], red[tid + s]);
            __syncthreads();
        }
        m = red[0]; __syncthreads();
        float sum = 0.f;
#pragma unroll
        for (int i = 0; i < 16; i++) { v[i] = expf(v[i] - m); sum += v[i]; }
        red[tid] = sum; __syncthreads();
        for (int s = 128; s; s >>= 1) {
            if (tid < s) red[tid] += red[tid + s];
            __syncthreads();
        }
        float r = 1.f / red[0];
#pragma unroll
        for (int i = 0; i < 16; i++)
            g_pa[(size_t)n * WH + i * 256 + tid] = v[i] * r;
    }
}

// ---------------------------------------------------------------------------
// K4: HMMA fp16 2-term GEMM.
// D[128,128] = Ah[128,K] @ (Bh+Bl)[K,128]; A=in*ca rounded to fp16 once;
// B pre-split exactly. Error ~ (A-Ah)·B ~ 2.8e-4 rms. fp32 reg accum.
// grid=(32 mtiles, 2 ntiles, 32 batch), block=256 (8 warps, warp tile 32x64).
// ---------------------------------------------------------------------------
#define KC 32
#define AST 40   // padded row stride in halves (80 bytes)

__global__ void __launch_bounds__(256)
k_conv_mma(const float* __restrict__ in, float* __restrict__ out) {
    __shared__ unsigned short Ah[128 * AST];
    __shared__ unsigned short Bh[128 * AST];
    __shared__ unsigned short Bl[128 * AST];
    __shared__ float cas[CC];

    const int tid = threadIdx.x, lane = tid & 31, wid = tid >> 5;
    const int nb = blockIdx.z;
    const int m0 = blockIdx.x * 128;
    const int n0 = blockIdx.y * 128;
    const int warp_m = (wid & 3) * 32;
    const int warp_n = (wid >> 2) * 64;

    cas[tid] = g_ca[nb * CC + tid];

    const float* A = in + ((size_t)nb * WH + m0) * CC;

    const uint32_t sAh = (uint32_t)__cvta_generic_to_shared(Ah);
    const uint32_t sBh = (uint32_t)__cvta_generic_to_shared(Bh);
    const uint32_t sBl = (uint32_t)__cvta_generic_to_shared(Bl);

    // ldmatrix per-thread address offsets (bytes)
    const int q = lane >> 3;
    const uint32_t aRow = (uint32_t)(warp_m + (lane & 7) + (q & 1) * 8) * 80
                        + (uint32_t)((q >> 1) * 8) * 2;
    const uint32_t bRow = (uint32_t)(warp_n + (lane & 7) + (q >> 1) * 8) * 80
                        + (uint32_t)((q & 1) * 8) * 2;

    // Global-load mappings
    const int rA = tid >> 1, sA = tid & 1;
    const int nB = tid >> 1, uB = tid & 1;

    float acc[2][8][4];
#pragma unroll
    for (int i = 0; i < 2; i++)
#pragma unroll
        for (int j = 0; j < 8; j++)
#pragma unroll
            for (int t = 0; t < 4; t++) acc[i][j][t] = 0.f;

    for (int c = 0; c < CC / KC; c++) {
        __syncthreads();
        // --- A chunk: fp32 load, fold ca, round to fp16, padded store ---
        {
            const float* Ar = A + (size_t)rA * CC + c * KC + sA * 16;
            const float* cp = cas + c * KC + sA * 16;
            uint32_t hi[8];
#pragma unroll
            for (int j = 0; j < 4; j++) {
                float4 v = *reinterpret_cast<const float4*>(Ar + j * 4);
                hi[j * 2 + 0] = pack_h2(v.x * cp[j * 4 + 0], v.y * cp[j * 4 + 1]);
                hi[j * 2 + 1] = pack_h2(v.z * cp[j * 4 + 2], v.w * cp[j * 4 + 3]);
            }
            uint4* dh = reinterpret_cast<uint4*>(&Ah[rA * AST + sA * 16]);
            dh[0] = make_uint4(hi[0], hi[1], hi[2], hi[3]);
            dh[1] = make_uint4(hi[4], hi[5], hi[6], hi[7]);
        }
        // --- B chunk: flat copy (L2-hot) ---
        {
            size_t gidx = (size_t)(n0 + nB) * CC + c * KC + uB * 16;
            const uint4* gh = reinterpret_cast<const uint4*>(g_Bh + gidx);
            const uint4* gl = reinterpret_cast<const uint4*>(g_Bl + gidx);
            uint4* dh = reinterpret_cast<uint4*>(&Bh[nB * AST + uB * 16]);
            uint4* dl = reinterpret_cast<uint4*>(&Bl[nB * AST + uB * 16]);
            dh[0] = gh[0]; dh[1] = gh[1];
            dl[0] = gl[0]; dl[1] = gl[1];
        }
        __syncthreads();

        // --- MMA: 2 k-steps x (AhBh + AhBl) ---
#pragma unroll
        for (int ks = 0; ks < 2; ks++) {
            const uint32_t ko = ks * 32;
            uint32_t ah[2][4];
            ldm4(ah[0], sAh + aRow + ko);
            ldm4(ah[1], sAh + aRow + 1280 + ko);
#pragma unroll
            for (int p = 0; p < 4; p++) {
                uint32_t bb[4];
                ldm4(bb, sBh + bRow + p * 1280 + ko);
                mma_f16(acc[0][2 * p],     ah[0], bb[0], bb[1]);
                mma_f16(acc[0][2 * p + 1], ah[0], bb[2], bb[3]);
                mma_f16(acc[1][2 * p],     ah[1], bb[0], bb[1]);
                mma_f16(acc[1][2 * p + 1], ah[1], bb[2], bb[3]);
                ldm4(bb, sBl + bRow + p * 1280 + ko);
                mma_f16(acc[0][2 * p],     ah[0], bb[0], bb[1]);
                mma_f16(acc[0][2 * p + 1], ah[0], bb[2], bb[3]);
                mma_f16(acc[1][2 * p],     ah[1], bb[0], bb[1]);
                mma_f16(acc[1][2 * p + 1], ah[1], bb[2], bb[3]);
            }
        }
    }

    // --- Epilogue: leaky0.1 then *pa, fp32 stores ---
#pragma unroll
    for (int mt = 0; mt < 2; mt++) {
        int mrow = m0 + warp_m + mt * 16 + (lane >> 2);
        float pa0 = g_pa[(size_t)nb * WH + mrow];
        float pa1 = g_pa[(size_t)nb * WH + mrow + 8];
        float* o0 = out + ((size_t)nb * WH + mrow) * CC + n0 + warp_n + (lane & 3) * 2;
        float* o1 = o0 + 8 * CC;
#pragma unroll
        for (int nt = 0; nt < 8; nt++) {
            float v0 = acc[mt][nt][0], v1 = acc[mt][nt][1];
            float v2 = acc[mt][nt][2], v3 = acc[mt][nt][3];
            v0 = (v0 > 0.f ? v0 : 0.1f * v0) * pa0;
            v1 = (v1 > 0.f ? v1 : 0.1f * v1) * pa0;
            v2 = (v2 > 0.f ? v2 : 0.1f * v2) * pa1;
            v3 = (v3 > 0.f ? v3 : 0.1f * v3) * pa1;
            *reinterpret_cast<float2*>(o0 + nt * 8) = make_float2(v0, v1);
            *reinterpret_cast<float2*>(o1 + nt * 8) = make_float2(v2, v3);
        }
    }
}

// ---------------------------------------------------------------------------
extern "C" void kernel_launch(void* const* d_in, const int* in_sizes, int n_in,
                              void* d_out, int out_size) {
    const float* in    = (const float*)d_in[0];  // [32,64,64,256]
    const float* style = (const float*)d_in[1];  // [32,256]
    const float* wd    = (const float*)d_in[2];  // [256,256]
    const float* wc    = (const float*)d_in[3];  // [1,1,256,256] -> [ci][co]
    float* out = (float*)d_out;

    k_prep<<<NN + CC, 256>>>(style, wd, wc);
    k_pa_colsum<<<dim3(16, NN), 256>>>(in);
    k_soft<<<2 * NN, 256>>>();
    k_conv_mma<<<dim3(WH / 128, CC / 128, NN), 256>>>(in, out);
}

// round 5
// speedup vs baseline: 2.3342x; 1.1602x over previous
#include <cuda_runtime.h>
#include <cuda_fp16.h>
#include <cstdint>

#define NN   32
#define WH   4096
#define CC   256
#define SCALE 0.0625f      // 1/sqrt(256)
#define BSCALE 64.0f       // pre-scale on B to keep lo-split out of subnormals
#define INV_BSCALE 0.015625f

// Scratch (device globals — no allocations allowed)
__device__ float g_q[NN * CC];
__device__ float g_partS[NN * 16 * CC];
__device__ float g_palog[NN * WH];
__device__ float g_ca[NN * CC];
__device__ float g_pa[NN * WH];
__device__ __align__(16) unsigned short g_Ah[(size_t)NN * WH * CC]; // fp16(inputs), 64MB
__device__ __align__(16) unsigned short g_Bh[NN * CC * CC];         // per-batch 64*ca*W hi
__device__ __align__(16) unsigned short g_Bl[NN * CC * CC];         // per-batch 64*ca*W lo

// ---------------------------------------------------------------------------
// Helpers (baseline PTX — plain sm_103 target)
// ---------------------------------------------------------------------------
__device__ __forceinline__ void ldm4(uint32_t* r, uint32_t addr) {
    asm volatile("ldmatrix.sync.aligned.m8n8.x4.shared.b16 {%0,%1,%2,%3}, [%4];"
                 : "=r"(r[0]), "=r"(r[1]), "=r"(r[2]), "=r"(r[3]) : "r"(addr));
}
__device__ __forceinline__ void mma_f16(float* c, const uint32_t* a,
                                        uint32_t b0, uint32_t b1) {
    asm volatile(
        "mma.sync.aligned.m16n8k16.row.col.f32.f16.f16.f32 "
        "{%0,%1,%2,%3}, {%4,%5,%6,%7}, {%8,%9}, {%0,%1,%2,%3};"
        : "+f"(c[0]), "+f"(c[1]), "+f"(c[2]), "+f"(c[3])
        : "r"(a[0]), "r"(a[1]), "r"(a[2]), "r"(a[3]), "r"(b0), "r"(b1));
}
__device__ __forceinline__ uint32_t pack_h2(float a, float b) {
    __half2 t = __floats2half2_rn(a, b);
    return *reinterpret_cast<uint32_t*>(&t);
}
__device__ __forceinline__ void cp16(uint32_t dst, const void* src) {
    asm volatile("cp.async.cg.shared.global [%0], [%1], 16;"
                 :: "r"(dst), "l"(src) : "memory");
}

// ---------------------------------------------------------------------------
// K1: q[n,c] = leaky_relu_0.3( style @ w_dense )
// ---------------------------------------------------------------------------
__global__ void k_q(const float* __restrict__ style, const float* __restrict__ wd) {
    int n = blockIdx.x, c = threadIdx.x;
    __shared__ float s[CC];
    s[c] = style[n * CC + c];
    __syncthreads();
    float acc = 0.f;
#pragma unroll 8
    for (int k = 0; k < CC; k++) acc = fmaf(s[k], wd[k * CC + c], acc);
    g_q[n * CC + c] = acc > 0.f ? acc : 0.3f * acc;
}

// ---------------------------------------------------------------------------
// K2: one pass over inputs: pa_logits + partial column sums + fp16 copy of A
// ---------------------------------------------------------------------------
__global__ void k_pa_colsum(const float* __restrict__ in) {
    int n = blockIdx.y, chunk = blockIdx.x;
    int tid = threadIdx.x, lane = tid & 31, w = tid >> 5;

    const float4* q4 = reinterpret_cast<const float4*>(g_q + (size_t)n * CC);
    float4 qa = q4[lane * 2], qb = q4[lane * 2 + 1];

    float4 cs0 = {0.f, 0.f, 0.f, 0.f}, cs1 = {0.f, 0.f, 0.f, 0.f};
    int pbase = chunk * 256 + w * 32;
    const float4* base4 =
        reinterpret_cast<const float4*>(in + ((size_t)n * WH + pbase) * CC);

    for (int i = 0; i < 32; i++) {
        const float4* r = base4 + (size_t)i * (CC / 4);
        float4 v0 = r[lane * 2], v1 = r[lane * 2 + 1];
        float d = v0.x * qa.x + v0.y * qa.y + v0.z * qa.z + v0.w * qa.w
                + v1.x * qb.x + v1.y * qb.y + v1.z * qb.z + v1.w * qb.w;
        cs0.x += v0.x; cs0.y += v0.y; cs0.z += v0.z; cs0.w += v0.w;
        cs1.x += v1.x; cs1.y += v1.y; cs1.z += v1.z; cs1.w += v1.w;
        // fp16 copy of the input (A operand for the conv GEMM)
        uint4 hc;
        hc.x = pack_h2(v0.x, v0.y); hc.y = pack_h2(v0.z, v0.w);
        hc.z = pack_h2(v1.x, v1.y); hc.w = pack_h2(v1.z, v1.w);
        *reinterpret_cast<uint4*>(
            g_Ah + ((size_t)n * WH + pbase + i) * CC + lane * 8) = hc;
#pragma unroll
        for (int o = 16; o; o >>= 1) d += __shfl_xor_sync(0xffffffffu, d, o);
        if (lane == 0) g_palog[(size_t)n * WH + pbase + i] = d * SCALE;
    }

    __shared__ float sm[8 * CC];
    float* smw = sm + w * CC + lane * 8;
    smw[0] = cs0.x; smw[1] = cs0.y; smw[2] = cs0.z; smw[3] = cs0.w;
    smw[4] = cs1.x; smw[5] = cs1.y; smw[6] = cs1.z; smw[7] = cs1.w;
    __syncthreads();
    float ssum = 0.f;
#pragma unroll
    for (int ww = 0; ww < 8; ww++) ssum += sm[ww * CC + tid];
    g_partS[((size_t)n * 16 + chunk) * CC + tid] = ssum;
}

// ---------------------------------------------------------------------------
// K3 (fused): blocks 0..31 -> channel softmax; 32..63 -> position softmax
// ---------------------------------------------------------------------------
__global__ void k_soft() {
    int b = blockIdx.x, tid = threadIdx.x;
    __shared__ float red[256];
    if (b < NN) {
        int n = b;
        float S = 0.f;
#pragma unroll
        for (int k = 0; k < 16; k++) S += g_partS[((size_t)n * 16 + k) * CC + tid];
        float logit = S * g_q[n * CC + tid] * SCALE;
        red[tid] = logit; __syncthreads();
        for (int s = 128; s; s >>= 1) {
            if (tid < s) red[tid] = fmaxf(red[tid], red[tid + s]);
            __syncthreads();
        }
        float m = red[0]; __syncthreads();
        float e = expf(logit - m);
        red[tid] = e; __syncthreads();
        for (int s = 128; s; s >>= 1) {
            if (tid < s) red[tid] += red[tid + s];
            __syncthreads();
        }
        g_ca[n * CC + tid] = e / red[0];
    } else {
        int n = b - NN;
        float v[16];
        float m = -1e30f;
#pragma unroll
        for (int i = 0; i < 16; i++) {
            v[i] = g_palog[(size_t)n * WH + i * 256 + tid];
            m = fmaxf(m, v[i]);
        }
        red[tid] = m; __syncthreads();
        for (int s = 128; s; s >>= 1) {
            if (tid < s) red[tid] = fmaxf(red[tid], red[tid + s]);
            __syncthreads();
        }
        m = red[0]; __syncthreads();
        float sum = 0.f;
#pragma unroll
        for (int i = 0; i < 16; i++) { v[i] = expf(v[i] - m); sum += v[i]; }
        red[tid] = sum; __syncthreads();
        for (int s = 128; s; s >>= 1) {
            if (tid < s) red[tid] += red[tid + s];
            __syncthreads();
        }
        float r = 1.f / red[0];
#pragma unroll
        for (int i = 0; i < 16; i++)
            g_pa[(size_t)n * WH + i * 256 + tid] = v[i] * r;
    }
}

// ---------------------------------------------------------------------------
// K_prepB: per-batch B_eff[co][ci] = 64*ca[n][ci]*W[ci][co], fp16 hi/lo split.
// grid=(8 ci-blocks, 32 n), block=256 (t = co).
// ---------------------------------------------------------------------------
__global__ void k_prepB(const float* __restrict__ wc) {
    int cb = blockIdx.x, n = blockIdx.y, t = threadIdx.x;
    int ci0 = cb * 32;
    const float* cap = g_ca + n * CC + ci0;
    uint32_t hi[16], lo[16];
#pragma unroll
    for (int j = 0; j < 32; j += 2) {
        float v0 = BSCALE * cap[j]     * wc[(size_t)(ci0 + j) * CC + t];
        float v1 = BSCALE * cap[j + 1] * wc[(size_t)(ci0 + j + 1) * CC + t];
        __half h0 = __float2half_rn(v0), h1 = __float2half_rn(v1);
        hi[j >> 1] = (uint32_t)__half_as_ushort(h0)
                   | ((uint32_t)__half_as_ushort(h1) << 16);
        lo[j >> 1] = pack_h2(v0 - __half2float(h0), v1 - __half2float(h1));
    }
    unsigned short* dh = g_Bh + ((size_t)n * CC + t) * CC + ci0;
    unsigned short* dl = g_Bl + ((size_t)n * CC + t) * CC + ci0;
#pragma unroll
    for (int j = 0; j < 4; j++) {
        reinterpret_cast<uint4*>(dh)[j] =
            make_uint4(hi[j * 4], hi[j * 4 + 1], hi[j * 4 + 2], hi[j * 4 + 3]);
        reinterpret_cast<uint4*>(dl)[j] =
            make_uint4(lo[j * 4], lo[j * 4 + 1], lo[j * 4 + 2], lo[j * 4 + 3]);
    }
}

// ---------------------------------------------------------------------------
// K4: HMMA fp16 2-term GEMM, CTA tile 128x256 (full C_out), warp tile 64x64.
// A = fp16(in) from g_Ah; B = per-batch folded 64*ca*W hi/lo.
// cp.async double-buffered K-chunks of 64. Epilogue: leaky0.1 * pa/64.
// grid=(32 mtiles, 32 batch), block=256.
// ---------------------------------------------------------------------------
#define RS     144                   // smem row stride (72 halves)
#define A_OFF  0
#define BH_OFF 18432
#define BL_OFF 55296
#define BUFB   92160
#define SMEMB  (2 * BUFB)            // 184320

__global__ void __launch_bounds__(256, 1)
k_conv_mma(float* __restrict__ out) {
    extern __shared__ char smem[];
    const uint32_t sb = (uint32_t)__cvta_generic_to_shared(smem);
    const int tid = threadIdx.x, lane = tid & 31, wid = tid >> 5;
    const int nb = blockIdx.y, m0 = blockIdx.x * 128;
    const int warp_m = (wid & 1) * 64, warp_n = (wid >> 1) * 64;
    const int q = lane >> 3;

    const uint32_t aBase = sb + A_OFF
        + (uint32_t)(warp_m + (lane & 7) + ((q & 1) << 3)) * RS + ((q >> 1) << 4);
    const uint32_t bBaseH = sb + BH_OFF
        + (uint32_t)(warp_n + (lane & 7) + ((q >> 1) << 3)) * RS + ((q & 1) << 4);
    const uint32_t bBaseL = bBaseH + (BL_OFF - BH_OFF);

    const unsigned short* Asrc  = g_Ah + ((size_t)nb * WH + m0) * CC;
    const unsigned short* BsrcH = g_Bh + (size_t)nb * CC * CC;
    const unsigned short* BsrcL = g_Bl + (size_t)nb * CC * CC;

    float acc[4][8][4];
#pragma unroll
    for (int i = 0; i < 4; i++)
#pragma unroll
        for (int j = 0; j < 8; j++)
#pragma unroll
            for (int t = 0; t < 4; t++) acc[i][j][t] = 0.f;

    auto issue = [&](int c, int buf) {
        uint32_t d = sb + (uint32_t)buf * BUFB;
#pragma unroll
        for (int j = 0; j < 4; j++) {
            int o = tid + 256 * j, row = o >> 3, seg = o & 7;
            cp16(d + A_OFF + row * RS + seg * 16,
                 Asrc + (size_t)row * CC + c * 64 + seg * 8);
        }
#pragma unroll
        for (int j = 0; j < 8; j++) {
            int o = tid + 256 * j, row = o >> 3, seg = o & 7;
            cp16(d + BH_OFF + row * RS + seg * 16,
                 BsrcH + (size_t)row * CC + c * 64 + seg * 8);
            cp16(d + BL_OFF + row * RS + seg * 16,
                 BsrcL + (size_t)row * CC + c * 64 + seg * 8);
        }
        asm volatile("cp.async.commit_group;" ::: "memory");
    };

    issue(0, 0);
    for (int c = 0; c < 4; c++) {
        const int buf = c & 1;
        if (c < 3) {
            issue(c + 1, buf ^ 1);
            asm volatile("cp.async.wait_group 1;" ::: "memory");
        } else {
            asm volatile("cp.async.wait_group 0;" ::: "memory");
        }
        __syncthreads();
        const uint32_t bo = (uint32_t)buf * BUFB;
#pragma unroll
        for (int ks = 0; ks < 4; ks++) {
            const uint32_t ko = bo + ks * 32;
            uint32_t ah[4][4];
#pragma unroll
            for (int mt = 0; mt < 4; mt++)
                ldm4(ah[mt], aBase + ko + mt * 16 * RS);
#pragma unroll
            for (int p = 0; p < 4; p++) {
                uint32_t bh[4], bl[4];
                ldm4(bh, bBaseH + ko + p * 16 * RS);
                ldm4(bl, bBaseL + ko + p * 16 * RS);
#pragma unroll
                for (int mt = 0; mt < 4; mt++) {
                    mma_f16(acc[mt][2 * p],     ah[mt], bh[0], bh[1]);
                    mma_f16(acc[mt][2 * p + 1], ah[mt], bh[2], bh[3]);
                    mma_f16(acc[mt][2 * p],     ah[mt], bl[0], bl[1]);
                    mma_f16(acc[mt][2 * p + 1], ah[mt], bl[2], bl[3]);
                }
            }
        }
        __syncthreads();
    }

    // --- Epilogue: leaky0.1 then * pa/64 (undo BSCALE; leaky is +homogeneous) ---
    const int g = lane >> 2, tg = lane & 3;
#pragma unroll
    for (int mt = 0; mt < 4; mt++) {
        int r0 = m0 + warp_m + mt * 16 + g;
        float pa0 = g_pa[(size_t)nb * WH + r0] * INV_BSCALE;
        float pa1 = g_pa[(size_t)nb * WH + r0 + 8] * INV_BSCALE;
        float* o0 = out + ((size_t)nb * WH + r0) * CC + warp_n + tg * 2;
        float* o1 = o0 + 8 * CC;
#pragma unroll
        for (int nt = 0; nt < 8; nt++) {
            float v0 = acc[mt][nt][0], v1 = acc[mt][nt][1];
            float v2 = acc[mt][nt][2], v3 = acc[mt][nt][3];
            v0 = (v0 > 0.f ? v0 : 0.1f * v0) * pa0;
            v1 = (v1 > 0.f ? v1 : 0.1f * v1) * pa0;
            v2 = (v2 > 0.f ? v2 : 0.1f * v2) * pa1;
            v3 = (v3 > 0.f ? v3 : 0.1f * v3) * pa1;
            *reinterpret_cast<float2*>(o0 + nt * 8) = make_float2(v0, v1);
            *reinterpret_cast<float2*>(o1 + nt * 8) = make_float2(v2, v3);
        }
    }
}

// ---------------------------------------------------------------------------
extern "C" void kernel_launch(void* const* d_in, const int* in_sizes, int n_in,
                              void* d_out, int out_size) {
    const float* in    = (const float*)d_in[0];  // [32,64,64,256]
    const float* style = (const float*)d_in[1];  // [32,256]
    const float* wd    = (const float*)d_in[2];  // [256,256]
    const float* wc    = (const float*)d_in[3];  // [1,1,256,256] -> [ci][co]
    float* out = (float*)d_out;

    static bool attr_set = false;
    if (!attr_set) {
        cudaFuncSetAttribute(k_conv_mma,
                             cudaFuncAttributeMaxDynamicSharedMemorySize, SMEMB);
        attr_set = true;
    }

    k_q<<<NN, CC>>>(style, wd);
    k_pa_colsum<<<dim3(16, NN), 256>>>(in);
    k_soft<<<2 * NN, 256>>>();
    k_prepB<<<dim3(8, NN), 256>>>(wc);
    k_conv_mma<<<dim3(WH / 128, NN), 256, SMEMB>>>(out);
}